// round 4
// baseline (speedup 1.0000x reference)
#include <cuda_runtime.h>
#include <math_constants.h>

// Global spatial max-pool: [B=64, H=56, W=56, C=256] f32 NHWC -> [B=64, C=256].
//
// R4: single-wave persistent grid + dynamic ticket scheduling.
//   Evidence (R2 vs R3): DRAM% pinned at ~74% regardless of occupancy/MLP ->
//   SM-side is not the limiter; remaining losses are wave quantization and
//   end-game imbalance. Fix: grid = 148*8 = 1184 CTAs (exactly one wave),
//   3584 tiles of 56KB pulled via a prefetched global ticket (ATOMG latency
//   hidden behind the current tile's streaming loads).
//   - tile id -> (b = tile/56, split = tile%56); partial slot fixed per tile,
//     so output is deterministic under any work assignment (max is
//     order-independent).
//   - per-batch completion counter: last tile of a batch does the 56-way
//     cross-split reduce inline and writes out[b].
//   - ticket + counters self-reset (last exiting CTA) for graph replay.
//   Kept: LDG.E.256 streaming loads, FMNMX.F32X2 packing, smem phase reduce.

#define B_DIM   64
#define HW      3136              // 56*56
#define C_DIM   256
#define SPLIT   56                // splits per batch
#define SPAN    (HW / SPLIT)      // 56 positions per tile (56 KB)
#define NTILES  (B_DIM * SPLIT)   // 3584
#define PHASES  8
#define ITERS   (SPAN / PHASES)   // 7
#define GRID    1184              // 148 SMs * 8 CTAs

__device__ float        g_partial[NTILES * C_DIM];   // 3.5 MB scratch
__device__ unsigned int g_bcount[B_DIM];             // splits done per batch
__device__ unsigned int g_ticket;                    // next dynamic tile - GRID
__device__ unsigned int g_done;                      // exited CTAs

__global__ __launch_bounds__(256, 8)
void gmax_persist(const float* __restrict__ in, float* __restrict__ out) {
    const int t = threadIdx.x;
    const int g = t & 31;                 // 8-channel group (32 bytes)
    const int p = t >> 5;                 // spatial phase 0..7

    __shared__ float        sm[PHASES * C_DIM];
    __shared__ unsigned int s_next;
    __shared__ unsigned int s_cnt;

    int tile = blockIdx.x;                // first tile is free

    while (tile < NTILES) {
        // Prefetch next ticket; latency hidden behind this tile's loads.
        if (t == 0)
            s_next = atomicAdd(&g_ticket, 1u) + GRID;

        const int b     = tile / SPLIT;
        const int split = tile - b * SPLIT;

        const float* __restrict__ base =
            in + (((size_t)(b * HW + split * SPAN + p)) << 8) + (g << 3);

        float a0 = -CUDART_INF_F, a1 = -CUDART_INF_F,
              a2 = -CUDART_INF_F, a3 = -CUDART_INF_F,
              a4 = -CUDART_INF_F, a5 = -CUDART_INF_F,
              a6 = -CUDART_INF_F, a7 = -CUDART_INF_F;

        #pragma unroll
        for (int i = 0; i < ITERS; ++i) {
            float v0, v1, v2, v3, v4, v5, v6, v7;
            asm volatile(
                "ld.global.nc.v8.f32 {%0,%1,%2,%3,%4,%5,%6,%7}, [%8];"
                : "=f"(v0), "=f"(v1), "=f"(v2), "=f"(v3),
                  "=f"(v4), "=f"(v5), "=f"(v6), "=f"(v7)
                : "l"(base + (size_t)i * (PHASES * C_DIM)));
            a0 = fmaxf(a0, v0);  a1 = fmaxf(a1, v1);
            a2 = fmaxf(a2, v2);  a3 = fmaxf(a3, v3);
            a4 = fmaxf(a4, v4);  a5 = fmaxf(a5, v5);
            a6 = fmaxf(a6, v6);  a7 = fmaxf(a7, v7);
        }

        // Cross-phase reduce through smem: sm[p*256 + c], conflict-free.
        float* my = sm + t * 8;           // == p*256 + g*8
        my[0] = a0; my[1] = a1; my[2] = a2; my[3] = a3;
        my[4] = a4; my[5] = a5; my[6] = a6; my[7] = a7;
        __syncthreads();

        {   // thread t == channel c
            float m = sm[t];
            #pragma unroll
            for (int ph = 1; ph < PHASES; ++ph)
                m = fmaxf(m, sm[ph * C_DIM + t]);
            g_partial[tile * C_DIM + t] = m;
        }

        // Mark tile complete; last tile of batch b does the final reduce.
        __threadfence();
        if (t == 0)
            s_cnt = atomicAdd(&g_bcount[b], 1u);
        __syncthreads();      // broadcasts s_cnt AND s_next; smem reusable after

        if (s_cnt == SPLIT - 1) {
            const float* part = g_partial + b * SPLIT * C_DIM;
            float m = part[t];
            #pragma unroll
            for (int s = 1; s < SPLIT; ++s)
                m = fmaxf(m, part[s * C_DIM + t]);
            out[b * C_DIM + t] = m;
            if (t == 0) g_bcount[b] = 0;  // self-reset for graph replay
        }

        tile = (int)s_next;
    }

    // Last CTA out resets the ticket for the next graph replay.
    if (t == 0) {
        unsigned int old = atomicAdd(&g_done, 1u);
        if (old == GRID - 1) {
            g_ticket = 0;
            g_done = 0;
        }
    }
}

extern "C" void kernel_launch(void* const* d_in, const int* in_sizes, int n_in,
                              void* d_out, int out_size) {
    const float* in  = (const float*)d_in[0];
    float*       out = (float*)d_out;
    gmax_persist<<<GRID, 256>>>(in, out);
}

// round 5
// speedup vs baseline: 1.2559x; 1.2559x over previous
#include <cuda_runtime.h>
#include <math_constants.h>

// Global spatial max-pool: [B=64, H=56, W=56, C=256] f32 NHWC -> [B=64, C=256].
//
// R5: back to the proven static-grid streaming shape (R4's persistent loop
// regressed 34% -> barriers inside the work loop drain the load pipe).
// Single change vs R3: tile size halved (SPLIT 28 -> 56, 3584 blocks of
// 56 KB). Serial depth per SM slot rises to ~3, shrinking the
// under-subscribed end-game tail that pinned R2/R3 at ~74% DRAM.
//   - LDG.E.256 (ld.global.nc.v8.f32) streaming loads, warp = 1 KB coalesced.
//   - fmaxf pairs pack to FMNMX.F32X2.
//   - unroll 2: enough MLP at occ 8 (128 KB in flight/SM vs ~26 KB needed),
//     avoids front-batch L1tex-queue spread.
//   - fused final reduce: last block per batch (threadfence + counter)
//     reduces the 56 partials; counters self-reset for graph replay.

#define B_DIM   64
#define HW      3136              // 56*56
#define C_DIM   256
#define SPLIT   56
#define SPAN    (HW / SPLIT)      // 56 positions per block (56 KB)
#define PHASES  8
#define ITERS   (SPAN / PHASES)   // 7

__device__ float        g_partial[B_DIM * SPLIT * C_DIM];  // 3.5 MB scratch
__device__ unsigned int g_count[B_DIM];                    // zero-init, self-resetting

__global__ __launch_bounds__(256, 8)
void gmax_fused(const float* __restrict__ in, float* __restrict__ out) {
    const int blk   = blockIdx.x;            // 0..3583
    const int b     = blk / SPLIT;
    const int split = blk - b * SPLIT;
    const int t     = threadIdx.x;
    const int g     = t & 31;                // 8-channel group (32 bytes)
    const int p     = t >> 5;                // spatial phase 0..7

    const float* __restrict__ base =
        in + (((size_t)(b * HW + split * SPAN + p)) << 8) + (g << 3);

    float a0 = -CUDART_INF_F, a1 = -CUDART_INF_F, a2 = -CUDART_INF_F, a3 = -CUDART_INF_F;
    float a4 = -CUDART_INF_F, a5 = -CUDART_INF_F, a6 = -CUDART_INF_F, a7 = -CUDART_INF_F;

    #pragma unroll 2
    for (int i = 0; i < ITERS; ++i) {
        float v0, v1, v2, v3, v4, v5, v6, v7;
        asm volatile(
            "ld.global.nc.v8.f32 {%0,%1,%2,%3,%4,%5,%6,%7}, [%8];"
            : "=f"(v0), "=f"(v1), "=f"(v2), "=f"(v3),
              "=f"(v4), "=f"(v5), "=f"(v6), "=f"(v7)
            : "l"(base + (size_t)i * (PHASES * C_DIM)));
        a0 = fmaxf(a0, v0);  a1 = fmaxf(a1, v1);
        a2 = fmaxf(a2, v2);  a3 = fmaxf(a3, v3);
        a4 = fmaxf(a4, v4);  a5 = fmaxf(a5, v5);
        a6 = fmaxf(a6, v6);  a7 = fmaxf(a7, v7);
    }

    // Cross-phase reduce through smem: sm[p*256 + c], conflict-free.
    __shared__ float sm[PHASES * C_DIM];
    float* my = sm + t * 8;  // == p*256 + g*8
    my[0] = a0; my[1] = a1; my[2] = a2; my[3] = a3;
    my[4] = a4; my[5] = a5; my[6] = a6; my[7] = a7;
    __syncthreads();

    // Thread t == channel c: reduce over 8 phases, write block partial.
    {
        float m = sm[t];
        #pragma unroll
        for (int ph = 1; ph < PHASES; ++ph)
            m = fmaxf(m, sm[ph * C_DIM + t]);
        g_partial[blk * C_DIM + t] = m;
    }

    // Last-block-per-batch does the cross-split reduce (fused 2nd stage).
    __threadfence();
    __shared__ bool amLast;
    if (t == 0) {
        unsigned int old = atomicAdd(&g_count[b], 1u);
        amLast = (old == SPLIT - 1);
    }
    __syncthreads();

    if (amLast) {
        const float* part = g_partial + b * SPLIT * C_DIM;
        float m = part[t];
        #pragma unroll
        for (int s = 1; s < SPLIT; ++s)
            m = fmaxf(m, part[s * C_DIM + t]);
        out[b * C_DIM + t] = m;
        if (t == 0) g_count[b] = 0;   // self-reset for next graph replay
    }
}

extern "C" void kernel_launch(void* const* d_in, const int* in_sizes, int n_in,
                              void* d_out, int out_size) {
    const float* in  = (const float*)d_in[0];
    float*       out = (float*)d_out;
    gmax_fused<<<B_DIM * SPLIT, 256>>>(in, out);
}

// round 6
// speedup vs baseline: 1.3322x; 1.0608x over previous
#include <cuda_runtime.h>
#include <math_constants.h>

// Global spatial max-pool: [B=64, H=56, W=56, C=256] f32 NHWC -> [B=64, C=256].
//
// R6: kill the per-block epilogue (the common fixed cost pinning R1-R5 at
// ~70-75% DRAM). Ownership remap: 128-thread blocks, thread t owns channel
// pair (2t, 2t+1) exclusively and streams ALL spatial positions of its tile
// with float2 loads. No cross-thread reduce -> no smem phase-reduce, no
// barrier on the accumulation path; epilogue = STG.64 partial + fence +
// counter. Warp still covers 256B contiguous (4 warps = full 1KB position).
//   - SPLIT=28: 1792 blocks x 128 thr (~48 warps/SM), SPAN=112 loads/thread.
//   - unroll 4: 4 outstanding LDG.64/warp -> ~48KB in flight/SM (need ~26KB).
//   - fused final reduce: last block per batch (threadfence + counter) reads
//     the 28 partials; counter self-resets for graph replay. Partials are
//     plain overwrites -> no reset hazard.

#define B_DIM   64
#define HW      3136              // 56*56
#define C_DIM   256
#define CP      128               // float2 channel pairs
#define SPLIT   28
#define SPAN    (HW / SPLIT)      // 112 positions per block
#define NBLK    (B_DIM * SPLIT)   // 1792

__device__ float2       g_partial[NBLK * CP];   // 1.75 MB scratch
__device__ unsigned int g_count[B_DIM];         // zero-init, self-resetting

__global__ __launch_bounds__(128, 16)
void gmax_fused(const float* __restrict__ in, float* __restrict__ out) {
    const int blk   = blockIdx.x;            // 0..1791
    const int b     = blk / SPLIT;
    const int split = blk - b * SPLIT;
    const int t     = threadIdx.x;           // channel pair id

    const float2* __restrict__ base =
        reinterpret_cast<const float2*>(in)
        + (size_t)(b * HW + split * SPAN) * CP + t;

    float2 m = make_float2(-CUDART_INF_F, -CUDART_INF_F);

    #pragma unroll 4
    for (int i = 0; i < SPAN; ++i) {
        float2 v = __ldg(base + (size_t)i * CP);
        m.x = fmaxf(m.x, v.x);
        m.y = fmaxf(m.y, v.y);
    }

    // Epilogue: direct partial write, no cross-thread reduce needed.
    g_partial[blk * CP + t] = m;

    __threadfence();
    __shared__ bool amLast;
    if (t == 0) {
        unsigned int old = atomicAdd(&g_count[b], 1u);
        amLast = (old == SPLIT - 1);
    }
    __syncthreads();

    // Last block of batch b reduces the 28 partials (coalesced reads).
    if (amLast) {
        const float2* part = g_partial + b * SPLIT * CP;
        float2 r = part[t];
        #pragma unroll
        for (int s = 1; s < SPLIT; ++s) {
            float2 p = part[s * CP + t];
            r.x = fmaxf(r.x, p.x);
            r.y = fmaxf(r.y, p.y);
        }
        reinterpret_cast<float2*>(out)[b * CP + t] = r;
        if (t == 0) g_count[b] = 0;   // self-reset for next graph replay
    }
}

extern "C" void kernel_launch(void* const* d_in, const int* in_sizes, int n_in,
                              void* d_out, int out_size) {
    const float* in  = (const float*)d_in[0];
    float*       out = (float*)d_out;
    gmax_fused<<<NBLK, 128>>>(in, out);
}

// round 7
// speedup vs baseline: 1.3333x; 1.0009x over previous
#include <cuda_runtime.h>
#include <math_constants.h>

// Global spatial max-pool: [B=64, H=56, W=56, C=256] f32 NHWC -> [B=64, C=256].
//
// R7: best-known shape (R3: SPLIT=28, 256 thr, LDG.E.256) plus:
//   1. CORRECTNESS: reader-side __threadfence() (acquire) in the fused final
//      reduce. R6 showed rel_err=3.2e-4 on a bit-exact max -> the last block
//      was reading partials without ordering against the release
//      (store+fence+atomicAdd) of producer blocks. Writer-release alone is
//      not enough; the consumer needs an acquire fence after observing the
//      counter.
//   2. Streaming cache policy: ld.global.nc.L1::no_allocate.L2::evict_first
//      -- the 205MB input has zero reuse; skip L1 allocation and mark L2
//      lines evict-first so the stream doesn't churn cache state.
//   3. unroll 4: steady-state MLP between R2 (28, spread-prone) and R3 (2).
// Epilogue: smem phase-reduce + last-block-per-batch final (counters
// self-reset for graph replay; max is order-independent).

#define B_DIM   64
#define HW      3136              // 56*56
#define C_DIM   256
#define SPLIT   28
#define SPAN    (HW / SPLIT)      // 112 spatial positions per block
#define PHASES  8
#define ITERS   (SPAN / PHASES)   // 14

__device__ float        g_partial[B_DIM * SPLIT * C_DIM];  // 1.75 MB scratch
__device__ unsigned int g_count[B_DIM];                    // zero-init, self-resetting

__global__ __launch_bounds__(256, 8)
void gmax_fused(const float* __restrict__ in, float* __restrict__ out) {
    const int blk   = blockIdx.x;            // 0..1791
    const int b     = blk / SPLIT;
    const int split = blk - b * SPLIT;
    const int t     = threadIdx.x;
    const int g     = t & 31;                // 8-channel group (32 bytes)
    const int p     = t >> 5;                // spatial phase 0..7

    const float* __restrict__ base =
        in + (((size_t)(b * HW + split * SPAN + p)) << 8) + (g << 3);

    float a0 = -CUDART_INF_F, a1 = -CUDART_INF_F, a2 = -CUDART_INF_F, a3 = -CUDART_INF_F;
    float a4 = -CUDART_INF_F, a5 = -CUDART_INF_F, a6 = -CUDART_INF_F, a7 = -CUDART_INF_F;

    #pragma unroll 4
    for (int i = 0; i < ITERS; ++i) {
        float v0, v1, v2, v3, v4, v5, v6, v7;
        asm volatile(
            "ld.global.nc.L1::no_allocate.L2::evict_first.v8.f32 "
            "{%0,%1,%2,%3,%4,%5,%6,%7}, [%8];"
            : "=f"(v0), "=f"(v1), "=f"(v2), "=f"(v3),
              "=f"(v4), "=f"(v5), "=f"(v6), "=f"(v7)
            : "l"(base + (size_t)i * (PHASES * C_DIM)));
        a0 = fmaxf(a0, v0);  a1 = fmaxf(a1, v1);
        a2 = fmaxf(a2, v2);  a3 = fmaxf(a3, v3);
        a4 = fmaxf(a4, v4);  a5 = fmaxf(a5, v5);
        a6 = fmaxf(a6, v6);  a7 = fmaxf(a7, v7);
    }

    // Cross-phase reduce through smem: sm[p*256 + c], conflict-free.
    __shared__ float sm[PHASES * C_DIM];
    float* my = sm + t * 8;  // == p*256 + g*8
    my[0] = a0; my[1] = a1; my[2] = a2; my[3] = a3;
    my[4] = a4; my[5] = a5; my[6] = a6; my[7] = a7;
    __syncthreads();

    // Thread t == channel c: reduce over 8 phases, write block partial.
    {
        float m = sm[t];
        #pragma unroll
        for (int ph = 1; ph < PHASES; ++ph)
            m = fmaxf(m, sm[ph * C_DIM + t]);
        g_partial[blk * C_DIM + t] = m;
    }

    // Release: make partial visible, then bump the batch counter.
    __threadfence();
    __shared__ bool amLast;
    if (t == 0) {
        unsigned int old = atomicAdd(&g_count[b], 1u);
        amLast = (old == SPLIT - 1);
    }
    __syncthreads();

    if (amLast) {
        // Acquire: order our reads of g_partial after the observed counter.
        __threadfence();
        const float* part = g_partial + b * SPLIT * C_DIM;
        float m = part[t];
        #pragma unroll
        for (int s = 1; s < SPLIT; ++s)
            m = fmaxf(m, part[s * C_DIM + t]);
        out[b * C_DIM + t] = m;
        if (t == 0) g_count[b] = 0;   // self-reset for next graph replay
    }
}

extern "C" void kernel_launch(void* const* d_in, const int* in_sizes, int n_in,
                              void* d_out, int out_size) {
    const float* in  = (const float*)d_in[0];
    float*       out = (float*)d_out;
    gmax_fused<<<B_DIM * SPLIT, 256>>>(in, out);
}